// round 4
// baseline (speedup 1.0000x reference)
#include <cuda_runtime.h>
#include <cstdint>

#define N_NODES 100000
#define N_EDGES 1600000
#define DIM 64
#define N_GRAPHS 2048
#define BN_EPS 1e-5f
#define NEG 0.01f

typedef unsigned long long ull;

// ---------------- scratch (device globals; no allocation allowed) ----------
__device__ float g_h1[N_NODES * DIM];
__device__ float g_h2[N_NODES * DIM];
__device__ float g_h3[N_NODES * DIM];
__device__ float g_agg[N_NODES * DIM];
__device__ float g_pool[N_GRAPHS * DIM];

// ---------------- f32x2 helpers (sm_100: 3-reg FFMA is half rate; FFMA2 full) ----
__device__ __forceinline__ ull ffma2(ull a, ull b, ull c) {
    ull d;
    asm("fma.rn.f32x2 %0, %1, %2, %3;" : "=l"(d) : "l"(a), "l"(b), "l"(c));
    return d;
}
__device__ __forceinline__ ull pk(float x, float y) {
    ull r;
    asm("mov.b64 %0, {%1,%2};" : "=l"(r) : "f"(x), "f"(y));
    return r;
}
__device__ __forceinline__ float2 upk(ull v) {
    float2 r;
    asm("mov.b64 {%0,%1}, %2;" : "=f"(r.x), "=f"(r.y) : "l"(v));
    return r;
}
__device__ __forceinline__ void red2(float* p, float a, float b) {
    asm volatile("red.global.add.v2.f32 [%0], {%1,%2};"
                 :: "l"(p), "f"(a), "f"(b) : "memory");
}
__device__ __forceinline__ void red4(float* p, float4 m) {
    asm volatile("red.global.add.v4.f32 [%0], {%1,%2,%3,%4};"
                 :: "l"(p), "f"(m.x), "f"(m.y), "f"(m.z), "f"(m.w) : "memory");
}

// ---------------- zero scratch ------------------------------------------------
__global__ void zero_kernel() {
    int t = blockIdx.x * blockDim.x + threadIdx.x;
    int stride = gridDim.x * blockDim.x;
    float4 z = {0.f, 0.f, 0.f, 0.f};
    for (int i = t; i < N_NODES * DIM / 4; i += stride) ((float4*)g_agg)[i] = z;
    for (int i = t; i < N_GRAPHS * DIM / 4; i += stride) ((float4*)g_pool)[i] = z;
}

// ---------------- edge kernel -------------------------------------------------
// agg[dst] += relu(x[src] + We @ ea + be).  One edge per WARP, 2 features/lane.
// Weights: 2 rows x 16 floats = 16 ull regs. x gather + red2 are 256B/warp coalesced.
__global__ void __launch_bounds__(256) edge_kernel(
    int xsel, const float* __restrict__ xext,
    const float* __restrict__ ea,
    const int* __restrict__ src, const int* __restrict__ dst,
    const float* __restrict__ We, const float* __restrict__ be)
{
    const float* xin = (xsel == 0) ? xext : (xsel == 1) ? g_h1 : g_h2;
    int gwarp = (blockIdx.x * blockDim.x + threadIdx.x) >> 5;
    int lane = threadIdx.x & 31;
    int f0 = lane * 2;
    int nwarps = (gridDim.x * blockDim.x) >> 5;

    ull w0[8], w1[8];
    {
        const ull* wr0 = (const ull*)(We + f0 * 16);
        const ull* wr1 = (const ull*)(We + (f0 + 1) * 16);
        #pragma unroll
        for (int p = 0; p < 8; p++) { w0[p] = __ldg(wr0 + p); w1[p] = __ldg(wr1 + p); }
    }
    float be0 = __ldg(be + f0), be1 = __ldg(be + f0 + 1);

    for (int e = gwarp; e < N_EDGES; e += nwarps) {
        int s = __ldg(src + e);
        int d = __ldg(dst + e);
        const ulonglong2* eau = (const ulonglong2*)(ea + (size_t)e * 16);
        ulonglong2 p0 = eau[0], p1 = eau[1], p2 = eau[2], p3 = eau[3];
        ull b[8] = {p0.x, p0.y, p1.x, p1.y, p2.x, p2.y, p3.x, p3.y};

        ull a0 = pk(be0, 0.f), a1 = pk(be1, 0.f);
        #pragma unroll
        for (int p = 0; p < 8; p++) {
            a0 = ffma2(w0[p], b[p], a0);
            a1 = ffma2(w1[p], b[p], a1);
        }
        float2 u0 = upk(a0), u1 = upk(a1);
        float e0 = u0.x + u0.y, e1 = u1.x + u1.y;

        float2 xr = *(const float2*)(xin + (size_t)s * DIM + f0);
        float m0 = fmaxf(xr.x + e0, 0.f);
        float m1 = fmaxf(xr.y + e1, 0.f);
        red2(g_agg + (size_t)d * DIM + f0, m0, m1);
    }
}

// ---------------- node kernel -------------------------------------------------
// hout = lrelu(BN((x + agg) @ W^T + b)); also re-zeroes agg for the next layer.
__global__ void __launch_bounds__(256) node_kernel(
    int xsel, const float* __restrict__ xext,
    const float* __restrict__ W, const float* __restrict__ b,
    const float* __restrict__ g, const float* __restrict__ bt,
    const float* __restrict__ mean, const float* __restrict__ var,
    int osel)
{
    const float* xin = (xsel == 0) ? xext : (xsel == 1) ? g_h1 : g_h2;
    float* hout = (osel == 1) ? g_h1 : (osel == 2) ? g_h2 : g_h3;

    __shared__ __align__(16) float ys[4][64];
    int tid = threadIdx.x;
    int f = tid & 63, slot = tid >> 6;

    ull w[32];
    const ull* wr = (const ull*)(W + f * 64);
    #pragma unroll
    for (int p = 0; p < 32; p++) w[p] = __ldg(wr + p);
    float bias = __ldg(b + f);
    float sc = __ldg(g + f) * rsqrtf(__ldg(var + f) + BN_EPS);
    float sh = __ldg(bt + f) - __ldg(mean + f) * sc;

    for (int base = blockIdx.x * 4; base < N_NODES; base += gridDim.x * 4) {
        int n = base + slot;
        size_t off = (size_t)n * 64 + f;
        ys[slot][f] = xin[off] + g_agg[off];
        g_agg[off] = 0.f;
        __syncthreads();
        const ulonglong2* yu = (const ulonglong2*)ys[slot];
        ull acc = pk(bias, 0.f);
        #pragma unroll
        for (int p = 0; p < 16; p++) {
            ulonglong2 y = yu[p];
            acc = ffma2(w[2 * p], y.x, acc);
            acc = ffma2(w[2 * p + 1], y.y, acc);
        }
        float2 u = upk(acc);
        float z = (u.x + u.y) * sc + sh;
        hout[off] = (z >= 0.f) ? z : NEG * z;
        __syncthreads();
    }
}

// ---------------- pool kernel -------------------------------------------------
__global__ void pool_kernel(const int* __restrict__ batch) {
    int t = blockIdx.x * blockDim.x + threadIdx.x;
    if (t >= N_NODES * 16) return;
    int n = t >> 4, q = t & 15;
    float4 v = *(const float4*)(g_h3 + (size_t)n * 64 + q * 4);
    int gi = __ldg(batch + n);
    red4(g_pool + (size_t)gi * 64 + q * 4, v);
}

// ---------------- final MLP kernel -------------------------------------------
// out[n] = Wl2 . lrelu(Wl1 @ [h1|h2|h3|pool[batch[n]]] + bl1) + bl2
// 512 thr, 64 nodes/block; per thread 4f x 8m. Coalesced Ws staging; strided a-loads
// conflict-free (stride 68 words). Small live set -> no spills under 128-reg cap.
#define WS_PAD 68
#define FINAL_SMEM ((256 * WS_PAD + 64 * 64) * 4)

__global__ void __launch_bounds__(512) final_kernel(
    const int* __restrict__ batch,
    const float* __restrict__ Wl1, const float* __restrict__ bl1,
    const float* __restrict__ Wl2, const float* __restrict__ bl2,
    float* __restrict__ out)
{
    extern __shared__ float smem[];
    float* Ws = smem;                 // [256][WS_PAD]
    float* vs = smem + 256 * WS_PAD;  // [64][64]

    int tid = threadIdx.x;
    int ft = tid & 31;
    int w = tid >> 5;
    int ng = w & 7;     // node group (8 nodes)
    int fh = w >> 3;    // feature half
    int nodeBase = blockIdx.x * 64;

    ull acc[4][8];
    #pragma unroll
    for (int i = 0; i < 4; i++) {
        float bb = __ldg(bl1 + fh * 128 + ft + 32 * i);
        #pragma unroll
        for (int m = 0; m < 8; m++) acc[i][m] = pk(bb, 0.f);
    }

    int r32 = tid >> 4;     // 0..31
    int pos = tid & 15;     // 0..15

    for (int c = 0; c < 4; c++) {
        __syncthreads();
        // stage Wl1 chunk coalesced: half-warp per 64-float row chunk
        #pragma unroll
        for (int it = 0; it < 8; it++) {
            int row = it * 32 + r32;
            float4 v = __ldg((const float4*)(Wl1 + (size_t)row * 256 + c * 64 + pos * 4));
            *(float4*)(Ws + row * WS_PAD + pos * 4) = v;
        }
        // stage v chunk: h1 / h2 / h3 / pool[batch]
        {
            const float* srcArr = (c == 0) ? g_h1 : (c == 1) ? g_h2 : (c == 2) ? g_h3 : g_pool;
            #pragma unroll
            for (int r = 0; r < 2; r++) {
                int idx = tid + 512 * r;
                int n = idx >> 4, k4 = idx & 15;
                int gn = nodeBase + n;
                float4 v = {0.f, 0.f, 0.f, 0.f};
                if (gn < N_NODES) {
                    size_t row = (c == 3) ? (size_t)__ldg(batch + gn) * 64 : (size_t)gn * 64;
                    v = *(const float4*)(srcArr + row + k4 * 4);
                }
                *(float4*)(vs + n * 64 + k4 * 4) = v;
            }
        }
        __syncthreads();

        const ulonglong2* Wsu2 = (const ulonglong2*)Ws;
        const ulonglong2* vsu2 = (const ulonglong2*)vs;
        #pragma unroll 2
        for (int kp2 = 0; kp2 < 16; kp2++) {
            ulonglong2 a0 = Wsu2[(fh * 128 + ft)       * (WS_PAD / 4) + kp2];
            ulonglong2 a1 = Wsu2[(fh * 128 + ft + 32)  * (WS_PAD / 4) + kp2];
            ulonglong2 a2 = Wsu2[(fh * 128 + ft + 64)  * (WS_PAD / 4) + kp2];
            ulonglong2 a3 = Wsu2[(fh * 128 + ft + 96)  * (WS_PAD / 4) + kp2];
            #pragma unroll
            for (int m = 0; m < 8; m++) {
                ulonglong2 bv = vsu2[(ng * 8 + m) * 16 + kp2];
                acc[0][m] = ffma2(a0.x, bv.x, acc[0][m]);
                acc[0][m] = ffma2(a0.y, bv.y, acc[0][m]);
                acc[1][m] = ffma2(a1.x, bv.x, acc[1][m]);
                acc[1][m] = ffma2(a1.y, bv.y, acc[1][m]);
                acc[2][m] = ffma2(a2.x, bv.x, acc[2][m]);
                acc[2][m] = ffma2(a2.y, bv.y, acc[2][m]);
                acc[3][m] = ffma2(a3.x, bv.x, acc[3][m]);
                acc[3][m] = ffma2(a3.y, bv.y, acc[3][m]);
            }
        }
    }

    // epilogue: lrelu + dot with Wl2, reduce across lanes and feature halves
    float wl2v[4];
    #pragma unroll
    for (int i = 0; i < 4; i++) wl2v[i] = __ldg(Wl2 + fh * 128 + ft + 32 * i);

    float po[8];
    #pragma unroll
    for (int m = 0; m < 8; m++) {
        float sum = 0.f;
        #pragma unroll
        for (int i = 0; i < 4; i++) {
            float2 u = upk(acc[i][m]);
            float zv = u.x + u.y;
            zv = (zv >= 0.f) ? zv : NEG * zv;
            sum += zv * wl2v[i];
        }
        po[m] = sum;
    }
    #pragma unroll
    for (int m = 0; m < 8; m++) {
        #pragma unroll
        for (int o = 16; o > 0; o >>= 1) po[m] += __shfl_xor_sync(0xffffffffu, po[m], o);
    }

    __shared__ float red[2][8][8];
    if (ft < 8) red[fh][ng][ft] = po[ft];
    __syncthreads();
    if (fh == 0 && ft < 8) {
        int gn = nodeBase + ng * 8 + ft;
        if (gn < N_NODES) out[gn] = red[0][ng][ft] + red[1][ng][ft] + bl2[0];
    }
}

// ---------------- launch ------------------------------------------------------
extern "C" void kernel_launch(void* const* d_in, const int* in_sizes, int n_in,
                              void* d_out, int out_size)
{
    const float* x     = (const float*)d_in[0];
    const int*   ei    = (const int*)d_in[1];
    const float* ea    = (const float*)d_in[2];
    const int*   batch = (const int*)d_in[3];

    const float* We[3] = {(const float*)d_in[4],  (const float*)d_in[12], (const float*)d_in[20]};
    const float* be[3] = {(const float*)d_in[5],  (const float*)d_in[13], (const float*)d_in[21]};
    const float* W[3]  = {(const float*)d_in[6],  (const float*)d_in[14], (const float*)d_in[22]};
    const float* b[3]  = {(const float*)d_in[7],  (const float*)d_in[15], (const float*)d_in[23]};
    const float* g[3]  = {(const float*)d_in[8],  (const float*)d_in[16], (const float*)d_in[24]};
    const float* bt[3] = {(const float*)d_in[9],  (const float*)d_in[17], (const float*)d_in[25]};
    const float* mn[3] = {(const float*)d_in[10], (const float*)d_in[18], (const float*)d_in[26]};
    const float* vr[3] = {(const float*)d_in[11], (const float*)d_in[19], (const float*)d_in[27]};
    const float* Wl1 = (const float*)d_in[28];
    const float* bl1 = (const float*)d_in[29];
    const float* Wl2 = (const float*)d_in[30];
    const float* bl2 = (const float*)d_in[31];
    float* out = (float*)d_out;

    const int* src = ei;
    const int* dst = ei + N_EDGES;

    cudaFuncSetAttribute(final_kernel, cudaFuncAttributeMaxDynamicSharedMemorySize, FINAL_SMEM);

    zero_kernel<<<2048, 256>>>();

    for (int l = 0; l < 3; l++) {
        edge_kernel<<<1184, 256>>>(l, x, ea, src, dst, We[l], be[l]);
        node_kernel<<<1024, 256>>>(l, x, W[l], b[l], g[l], bt[l], mn[l], vr[l], l + 1);
    }

    pool_kernel<<<(N_NODES * 16 + 255) / 256, 256>>>(batch);

    final_kernel<<<(N_NODES + 63) / 64, 512, FINAL_SMEM>>>(batch, Wl1, bl1, Wl2, bl2, out);
}

// round 5
// speedup vs baseline: 1.2459x; 1.2459x over previous
#include <cuda_runtime.h>
#include <cstdint>

#define N_NODES 100000
#define N_EDGES 1600000
#define DIM 64
#define N_GRAPHS 2048
#define BN_EPS 1e-5f
#define NEG 0.01f

typedef unsigned long long ull;

// ---------------- scratch (device globals; no allocation allowed) ----------
__device__ float g_h1[N_NODES * DIM];
__device__ float g_h2[N_NODES * DIM];
__device__ float g_h3[N_NODES * DIM];
__device__ float g_agg[N_NODES * DIM];
__device__ float g_pool[N_GRAPHS * DIM];
__device__ float g_WT[256 * 256];     // Wl1 transposed: WT[k][f]

// ---------------- f32x2 helpers (sm_100: 3-reg FFMA is half rate; FFMA2 full) ----
__device__ __forceinline__ ull ffma2(ull a, ull b, ull c) {
    ull d;
    asm("fma.rn.f32x2 %0, %1, %2, %3;" : "=l"(d) : "l"(a), "l"(b), "l"(c));
    return d;
}
__device__ __forceinline__ ull pk(float x, float y) {
    ull r;
    asm("mov.b64 %0, {%1,%2};" : "=l"(r) : "f"(x), "f"(y));
    return r;
}
__device__ __forceinline__ float2 upk(ull v) {
    float2 r;
    asm("mov.b64 {%0,%1}, %2;" : "=f"(r.x), "=f"(r.y) : "l"(v));
    return r;
}
__device__ __forceinline__ void red4(float* p, float4 m) {
    asm volatile("red.global.add.v4.f32 [%0], {%1,%2,%3,%4};"
                 :: "l"(p), "f"(m.x), "f"(m.y), "f"(m.z), "f"(m.w) : "memory");
}

// ---------------- zero scratch ------------------------------------------------
__global__ void zero_kernel() {
    int t = blockIdx.x * blockDim.x + threadIdx.x;
    int stride = gridDim.x * blockDim.x;
    float4 z = {0.f, 0.f, 0.f, 0.f};
    for (int i = t; i < N_NODES * DIM / 4; i += stride) ((float4*)g_agg)[i] = z;
    for (int i = t; i < N_GRAPHS * DIM / 4; i += stride) ((float4*)g_pool)[i] = z;
}

// ---------------- Wl1 transpose prep (runs once per launch; ~5us) -------------
__global__ void transpose_wl1(const float* __restrict__ Wl1) {
    __shared__ float tile[32][33];
    int bx = blockIdx.x & 7, by = blockIdx.x >> 3;   // 8x8 blocks of 32x32
    int tx = threadIdx.x & 31, ty = threadIdx.x >> 5; // 32x8 threads
    #pragma unroll
    for (int j = 0; j < 32; j += 8)
        tile[ty + j][tx] = Wl1[(size_t)(by * 32 + ty + j) * 256 + bx * 32 + tx];
    __syncthreads();
    #pragma unroll
    for (int j = 0; j < 32; j += 8)
        g_WT[(size_t)(bx * 32 + ty + j) * 256 + by * 32 + tx] = tile[tx][ty + j];
}

// ---------------- edge kernel (Round-2 design: measured 182us) -----------------
// agg[dst] += relu(x[src] + We @ ea + be).  16 lanes per edge, 4 features each.
__global__ void __launch_bounds__(256) edge_kernel(
    int xsel, const float* __restrict__ xext,
    const float* __restrict__ ea,
    const int* __restrict__ src, const int* __restrict__ dst,
    const float* __restrict__ We, const float* __restrict__ be)
{
    const float* xin = (xsel == 0) ? xext : (xsel == 1) ? g_h1 : g_h2;
    int t = blockIdx.x * blockDim.x + threadIdx.x;
    int fq = t & 15;
    int f0 = fq * 4;
    int e0 = t >> 4;
    int estep = (gridDim.x * blockDim.x) >> 4;

    ull w[4][8];
    #pragma unroll
    for (int i = 0; i < 4; i++) {
        const ull* wr = (const ull*)(We + (f0 + i) * 16);
        #pragma unroll
        for (int p = 0; p < 8; p++) w[i][p] = __ldg(wr + p);
    }
    ull accInit[4];
    #pragma unroll
    for (int i = 0; i < 4; i++) accInit[i] = pk(__ldg(be + f0 + i), 0.f);

    for (int e = e0; e < N_EDGES; e += estep) {
        int s = __ldg(src + e);
        int d = __ldg(dst + e);
        const ulonglong2* eau = (const ulonglong2*)(ea + (size_t)e * 16);
        ulonglong2 p0 = eau[0], p1 = eau[1], p2 = eau[2], p3 = eau[3];
        ull b[8] = {p0.x, p0.y, p1.x, p1.y, p2.x, p2.y, p3.x, p3.y};

        float ev[4];
        #pragma unroll
        for (int i = 0; i < 4; i++) {
            ull acc = accInit[i];
            #pragma unroll
            for (int p = 0; p < 8; p++) acc = ffma2(w[i][p], b[p], acc);
            float2 u = upk(acc);
            ev[i] = u.x + u.y;
        }
        float4 xr = *(const float4*)(xin + (size_t)s * DIM + f0);
        float4 m;
        m.x = fmaxf(xr.x + ev[0], 0.f);
        m.y = fmaxf(xr.y + ev[1], 0.f);
        m.z = fmaxf(xr.z + ev[2], 0.f);
        m.w = fmaxf(xr.w + ev[3], 0.f);
        red4(g_agg + (size_t)d * DIM + f0, m);
    }
}

// ---------------- node kernel -------------------------------------------------
__global__ void __launch_bounds__(256) node_kernel(
    int xsel, const float* __restrict__ xext,
    const float* __restrict__ W, const float* __restrict__ b,
    const float* __restrict__ g, const float* __restrict__ bt,
    const float* __restrict__ mean, const float* __restrict__ var,
    int osel)
{
    const float* xin = (xsel == 0) ? xext : (xsel == 1) ? g_h1 : g_h2;
    float* hout = (osel == 1) ? g_h1 : (osel == 2) ? g_h2 : g_h3;

    __shared__ __align__(16) float ys[4][64];
    int tid = threadIdx.x;
    int f = tid & 63, slot = tid >> 6;

    ull w[32];
    const ull* wr = (const ull*)(W + f * 64);
    #pragma unroll
    for (int p = 0; p < 32; p++) w[p] = __ldg(wr + p);
    float bias = __ldg(b + f);
    float sc = __ldg(g + f) * rsqrtf(__ldg(var + f) + BN_EPS);
    float sh = __ldg(bt + f) - __ldg(mean + f) * sc;

    for (int base = blockIdx.x * 4; base < N_NODES; base += gridDim.x * 4) {
        int n = base + slot;
        size_t off = (size_t)n * 64 + f;
        ys[slot][f] = xin[off] + g_agg[off];
        g_agg[off] = 0.f;
        __syncthreads();
        const ulonglong2* yu = (const ulonglong2*)ys[slot];
        ull acc = pk(bias, 0.f);
        #pragma unroll
        for (int p = 0; p < 16; p++) {
            ulonglong2 y = yu[p];
            acc = ffma2(w[2 * p], y.x, acc);
            acc = ffma2(w[2 * p + 1], y.y, acc);
        }
        float2 u = upk(acc);
        float z = (u.x + u.y) * sc + sh;
        hout[off] = (z >= 0.f) ? z : NEG * z;
        __syncthreads();
    }
}

// ---------------- pool kernel -------------------------------------------------
__global__ void pool_kernel(const int* __restrict__ batch) {
    int t = blockIdx.x * blockDim.x + threadIdx.x;
    if (t >= N_NODES * 16) return;
    int n = t >> 4, q = t & 15;
    float4 v = *(const float4*)(g_h3 + (size_t)n * 64 + q * 4);
    int gi = __ldg(batch + n);
    red4(g_pool + (size_t)gi * 64 + q * 4, v);
}

// ---------------- final MLP kernel -------------------------------------------
// out[n] = Wl2 . lrelu(Wl1 @ [h1|h2|h3|pool[batch[n]]] + bl1) + bl2
// f32x2 packed over FEATURES: each acc ull = 2 adjacent outputs; acc[2][8] = 32 regs.
// Wl1 pre-transposed (g_WT, k-major), staged as Ws2[64k][256f].
// v staged duplicated (v,v) so hot loop reads one uniform LDS.128 per (m, 2k).
#define FINAL_SMEM ((64 * 256 + 64 * 64 * 2) * 4)   // 64KB Ws2 + 32KB vs2 = 96KB

__global__ void __launch_bounds__(512) final_kernel(
    const int* __restrict__ batch,
    const float* __restrict__ bl1,
    const float* __restrict__ Wl2, const float* __restrict__ bl2,
    float* __restrict__ out)
{
    extern __shared__ float smem[];
    float* Ws2 = smem;                // [64 k][256 f]
    float* vs2 = smem + 64 * 256;     // [64 nodes][64 k] duplicated float2

    int tid = threadIdx.x;
    int ft = tid & 31;
    int w = tid >> 5;
    int ng = w & 7;     // node group (8 nodes)
    int fh = w >> 3;    // feature half (0 or 1)
    int nodeBase = blockIdx.x * 64;

    int fA = fh * 128 + 2 * ft;        // outputs fA, fA+1
    int fB = fA + 64;                  // outputs fB, fB+1

    ull biasA = *(const ull*)(bl1 + fA);
    ull biasB = *(const ull*)(bl1 + fB);

    ull acc[2][8];
    #pragma unroll
    for (int m = 0; m < 8; m++) { acc[0][m] = biasA; acc[1][m] = biasB; }

    for (int c = 0; c < 4; c++) {
        __syncthreads();
        // stage Ws2: rows c*64..c*64+63 of WT (k-major), fully coalesced float4 copy
        #pragma unroll
        for (int it = 0; it < 8; it++) {
            int idx = it * 512 + tid;          // 0..4095 float4s
            int r = idx >> 6, c4 = idx & 63;
            float4 v = *(const float4*)(g_WT + (size_t)(c * 64 + r) * 256 + c4 * 4);
            *(float4*)(Ws2 + r * 256 + c4 * 4) = v;
        }
        // stage vs2 duplicated: h1/h2/h3/pool[batch] features c*64..c*64+63
        {
            const float* srcArr = (c == 0) ? g_h1 : (c == 1) ? g_h2 : (c == 2) ? g_h3 : g_pool;
            #pragma unroll
            for (int it = 0; it < 8; it++) {
                int idx = it * 512 + tid;       // 0..4095 scalars
                int n = idx >> 6, k = idx & 63;
                int gn = nodeBase + n;
                float v = 0.f;
                if (gn < N_NODES) {
                    size_t row = (c == 3) ? (size_t)__ldg(batch + gn) * 64 : (size_t)gn * 64;
                    v = srcArr[row + k];
                }
                *(float2*)(vs2 + (n * 64 + k) * 2) = make_float2(v, v);
            }
        }
        __syncthreads();

        #pragma unroll 2
        for (int k = 0; k < 64; k += 2) {
            ull a0k0 = *(const ull*)(Ws2 + k * 256 + fA);
            ull a1k0 = *(const ull*)(Ws2 + k * 256 + fB);
            ull a0k1 = *(const ull*)(Ws2 + (k + 1) * 256 + fA);
            ull a1k1 = *(const ull*)(Ws2 + (k + 1) * 256 + fB);
            const ulonglong2* bvp = (const ulonglong2*)(vs2 + (ng * 8 * 64 + k) * 2);
            #pragma unroll
            for (int m = 0; m < 8; m++) {
                ulonglong2 bv = bvp[m * 32];   // (v_k,v_k, v_k1,v_k1)
                acc[0][m] = ffma2(a0k0, bv.x, acc[0][m]);
                acc[0][m] = ffma2(a0k1, bv.y, acc[0][m]);
                acc[1][m] = ffma2(a1k0, bv.x, acc[1][m]);
                acc[1][m] = ffma2(a1k1, bv.y, acc[1][m]);
            }
        }
    }

    // epilogue: lrelu + dot with Wl2 (each acc half is a distinct output)
    float2 wA = *(const float2*)(Wl2 + fA);
    float2 wB = *(const float2*)(Wl2 + fB);

    float po[8];
    #pragma unroll
    for (int m = 0; m < 8; m++) {
        float2 uA = upk(acc[0][m]);
        float2 uB = upk(acc[1][m]);
        float zA0 = (uA.x >= 0.f) ? uA.x : NEG * uA.x;
        float zA1 = (uA.y >= 0.f) ? uA.y : NEG * uA.y;
        float zB0 = (uB.x >= 0.f) ? uB.x : NEG * uB.x;
        float zB1 = (uB.y >= 0.f) ? uB.y : NEG * uB.y;
        po[m] = zA0 * wA.x + zA1 * wA.y + zB0 * wB.x + zB1 * wB.y;
    }
    #pragma unroll
    for (int m = 0; m < 8; m++) {
        #pragma unroll
        for (int o = 16; o > 0; o >>= 1) po[m] += __shfl_xor_sync(0xffffffffu, po[m], o);
    }

    __shared__ float redsm[2][8][8];
    if (ft < 8) redsm[fh][ng][ft] = po[ft];
    __syncthreads();
    if (fh == 0 && ft < 8) {
        int gn = nodeBase + ng * 8 + ft;
        if (gn < N_NODES) out[gn] = redsm[0][ng][ft] + redsm[1][ng][ft] + bl2[0];
    }
}

// ---------------- launch ------------------------------------------------------
extern "C" void kernel_launch(void* const* d_in, const int* in_sizes, int n_in,
                              void* d_out, int out_size)
{
    const float* x     = (const float*)d_in[0];
    const int*   ei    = (const int*)d_in[1];
    const float* ea    = (const float*)d_in[2];
    const int*   batch = (const int*)d_in[3];

    const float* We[3] = {(const float*)d_in[4],  (const float*)d_in[12], (const float*)d_in[20]};
    const float* be[3] = {(const float*)d_in[5],  (const float*)d_in[13], (const float*)d_in[21]};
    const float* W[3]  = {(const float*)d_in[6],  (const float*)d_in[14], (const float*)d_in[22]};
    const float* b[3]  = {(const float*)d_in[7],  (const float*)d_in[15], (const float*)d_in[23]};
    const float* g[3]  = {(const float*)d_in[8],  (const float*)d_in[16], (const float*)d_in[24]};
    const float* bt[3] = {(const float*)d_in[9],  (const float*)d_in[17], (const float*)d_in[25]};
    const float* mn[3] = {(const float*)d_in[10], (const float*)d_in[18], (const float*)d_in[26]};
    const float* vr[3] = {(const float*)d_in[11], (const float*)d_in[19], (const float*)d_in[27]};
    const float* Wl1 = (const float*)d_in[28];
    const float* bl1 = (const float*)d_in[29];
    const float* Wl2 = (const float*)d_in[30];
    const float* bl2 = (const float*)d_in[31];
    float* out = (float*)d_out;

    const int* src = ei;
    const int* dst = ei + N_EDGES;

    cudaFuncSetAttribute(final_kernel, cudaFuncAttributeMaxDynamicSharedMemorySize, FINAL_SMEM);

    zero_kernel<<<2048, 256>>>();
    transpose_wl1<<<64, 256>>>(Wl1);

    for (int l = 0; l < 3; l++) {
        edge_kernel<<<592, 256>>>(l, x, ea, src, dst, We[l], be[l]);
        node_kernel<<<1024, 256>>>(l, x, W[l], b[l], g[l], bt[l], mn[l], vr[l], l + 1);
    }

    pool_kernel<<<(N_NODES * 16 + 255) / 256, 256>>>(batch);

    final_kernel<<<(N_NODES + 63) / 64, 512, FINAL_SMEM>>>(batch, bl1, Wl2, bl2, out);
}

// round 6
// speedup vs baseline: 1.3749x; 1.1035x over previous
#include <cuda_runtime.h>
#include <cstdint>

#define N_NODES 100000
#define N_EDGES 1600000
#define DIM 64
#define N_GRAPHS 2048
#define BN_EPS 1e-5f
#define NEG 0.01f

typedef unsigned long long ull;

// ---------------- scratch (device globals; no allocation allowed) ----------
__device__ float g_h1[N_NODES * DIM];
__device__ float g_h2[N_NODES * DIM];
__device__ float g_h3[N_NODES * DIM];
__device__ float g_agg[N_NODES * DIM];
__device__ float g_pool[N_GRAPHS * DIM];
__device__ float g_WT[256 * 256];        // Wl1 transposed: WT[k][f]
__device__ float g_WT64[3][64 * 64];     // node-layer W transposed: WT64[l][k][f]

// ---------------- f32x2 helpers (sm_100: 3-reg FFMA half rate; FFMA2 full) ----
__device__ __forceinline__ ull ffma2(ull a, ull b, ull c) {
    ull d;
    asm("fma.rn.f32x2 %0, %1, %2, %3;" : "=l"(d) : "l"(a), "l"(b), "l"(c));
    return d;
}
__device__ __forceinline__ ull pk(float x, float y) {
    ull r;
    asm("mov.b64 %0, {%1,%2};" : "=l"(r) : "f"(x), "f"(y));
    return r;
}
__device__ __forceinline__ float2 upk(ull v) {
    float2 r;
    asm("mov.b64 {%0,%1}, %2;" : "=f"(r.x), "=f"(r.y) : "l"(v));
    return r;
}
__device__ __forceinline__ void red4(float* p, float4 m) {
    asm volatile("red.global.add.v4.f32 [%0], {%1,%2,%3,%4};"
                 :: "l"(p), "f"(m.x), "f"(m.y), "f"(m.z), "f"(m.w) : "memory");
}

// ---------------- zero scratch ------------------------------------------------
__global__ void zero_kernel() {
    int t = blockIdx.x * blockDim.x + threadIdx.x;
    int stride = gridDim.x * blockDim.x;
    float4 z = {0.f, 0.f, 0.f, 0.f};
    for (int i = t; i < N_NODES * DIM / 4; i += stride) ((float4*)g_agg)[i] = z;
    for (int i = t; i < N_GRAPHS * DIM / 4; i += stride) ((float4*)g_pool)[i] = z;
}

// ---------------- Wl1 transpose prep (once per launch) ------------------------
__global__ void transpose_wl1(const float* __restrict__ Wl1) {
    __shared__ float tile[32][33];
    int bx = blockIdx.x & 7, by = blockIdx.x >> 3;
    int tx = threadIdx.x & 31, ty = threadIdx.x >> 5;
    #pragma unroll
    for (int j = 0; j < 32; j += 8)
        tile[ty + j][tx] = Wl1[(size_t)(by * 32 + ty + j) * 256 + bx * 32 + tx];
    __syncthreads();
    #pragma unroll
    for (int j = 0; j < 32; j += 8)
        g_WT[(size_t)(bx * 32 + ty + j) * 256 + by * 32 + tx] = tile[tx][ty + j];
}

// ---------------- node-layer W transpose (one block per layer) -----------------
__global__ void transpose_w64(const float* __restrict__ W0,
                              const float* __restrict__ W1,
                              const float* __restrict__ W2) {
    const float* W = (blockIdx.x == 0) ? W0 : (blockIdx.x == 1) ? W1 : W2;
    __shared__ float tile[64][65];
    int tid = threadIdx.x;
    #pragma unroll
    for (int i = 0; i < 16; i++) {
        int idx = i * 256 + tid;
        int f = idx >> 6, k = idx & 63;
        tile[k][f] = W[f * 64 + k];
    }
    __syncthreads();
    #pragma unroll
    for (int i = 0; i < 16; i++) {
        int idx = i * 256 + tid;
        int k = idx >> 6, f = idx & 63;
        g_WT64[blockIdx.x][k * 64 + f] = tile[k][f];
    }
}

// ---------------- edge kernel (Round-2 design: measured 182us) -----------------
__global__ void __launch_bounds__(256) edge_kernel(
    int xsel, const float* __restrict__ xext,
    const float* __restrict__ ea,
    const int* __restrict__ src, const int* __restrict__ dst,
    const float* __restrict__ We, const float* __restrict__ be)
{
    const float* xin = (xsel == 0) ? xext : (xsel == 1) ? g_h1 : g_h2;
    int t = blockIdx.x * blockDim.x + threadIdx.x;
    int fq = t & 15;
    int f0 = fq * 4;
    int e0 = t >> 4;
    int estep = (gridDim.x * blockDim.x) >> 4;

    ull w[4][8];
    #pragma unroll
    for (int i = 0; i < 4; i++) {
        const ull* wr = (const ull*)(We + (f0 + i) * 16);
        #pragma unroll
        for (int p = 0; p < 8; p++) w[i][p] = __ldg(wr + p);
    }
    ull accInit[4];
    #pragma unroll
    for (int i = 0; i < 4; i++) accInit[i] = pk(__ldg(be + f0 + i), 0.f);

    for (int e = e0; e < N_EDGES; e += estep) {
        int s = __ldg(src + e);
        int d = __ldg(dst + e);
        const ulonglong2* eau = (const ulonglong2*)(ea + (size_t)e * 16);
        ulonglong2 p0 = eau[0], p1 = eau[1], p2 = eau[2], p3 = eau[3];
        ull b[8] = {p0.x, p0.y, p1.x, p1.y, p2.x, p2.y, p3.x, p3.y};

        float ev[4];
        #pragma unroll
        for (int i = 0; i < 4; i++) {
            ull acc = accInit[i];
            #pragma unroll
            for (int p = 0; p < 8; p++) acc = ffma2(w[i][p], b[p], acc);
            float2 u = upk(acc);
            ev[i] = u.x + u.y;
        }
        float4 xr = *(const float4*)(xin + (size_t)s * DIM + f0);
        float4 m;
        m.x = fmaxf(xr.x + ev[0], 0.f);
        m.y = fmaxf(xr.y + ev[1], 0.f);
        m.z = fmaxf(xr.z + ev[2], 0.f);
        m.w = fmaxf(xr.w + ev[3], 0.f);
        red4(g_agg + (size_t)d * DIM + f0, m);
    }
}

// ---------------- node kernel: tiled GEMM, f32x2 packed over features ----------
// hout = lrelu(BN((x+agg) @ W^T + b)); re-zeroes agg. 64 nodes/block, 256 thr.
// Warp w handles nodes w*8..w*8+7; lane ft covers outputs (2ft, 2ft+1).
// 8 independent accumulators -> latency hidden; W^T + duplicated y in smem.
__global__ void __launch_bounds__(256) node_kernel(
    int xsel, const float* __restrict__ xext,
    int layer, const float* __restrict__ b,
    const float* __restrict__ g, const float* __restrict__ bt,
    const float* __restrict__ mean, const float* __restrict__ var,
    int osel)
{
    const float* xin = (xsel == 0) ? xext : (xsel == 1) ? g_h1 : g_h2;
    float* hout = (osel == 1) ? g_h1 : (osel == 2) ? g_h2 : g_h3;
    const float* WT = g_WT64[layer];

    __shared__ __align__(16) float Wt2[64 * 64];      // [k][f] 16KB
    __shared__ __align__(16) float vs2[64 * 64 * 2];  // [n][k] duplicated, 32KB

    int tid = threadIdx.x;
    int ft = tid & 31;
    int w = tid >> 5;                 // warp 0..7
    int nodeBase = blockIdx.x * 64;

    // stage W^T coalesced (float4)
    #pragma unroll
    for (int i = 0; i < 4; i++) {
        int idx = i * 256 + tid;      // 0..1023 float4s
        ((float4*)Wt2)[idx] = ((const float4*)WT)[idx];
    }
    // stage y = x + agg, duplicated (v,v); also zero agg
    #pragma unroll
    for (int i = 0; i < 16; i++) {
        int idx = i * 256 + tid;      // 0..4095 scalars
        int n = idx >> 6, k = idx & 63;
        int gn = nodeBase + n;
        float v = 0.f;
        if (gn < N_NODES) {
            size_t off = (size_t)gn * 64 + k;
            v = xin[off] + g_agg[off];
            g_agg[off] = 0.f;
        }
        *(float2*)(vs2 + (n * 64 + k) * 2) = make_float2(v, v);
    }
    __syncthreads();

    ull bias2 = *(const ull*)(b + 2 * ft);
    ull acc[8];
    #pragma unroll
    for (int m = 0; m < 8; m++) acc[m] = bias2;

    #pragma unroll 2
    for (int k = 0; k < 64; k += 2) {
        ull a0 = *(const ull*)(Wt2 + k * 64 + 2 * ft);
        ull a1 = *(const ull*)(Wt2 + (k + 1) * 64 + 2 * ft);
        #pragma unroll
        for (int m = 0; m < 8; m++) {
            const ulonglong2* bp = (const ulonglong2*)(vs2 + (w * 8 + m) * 128);
            ulonglong2 bv = bp[k >> 1];
            acc[m] = ffma2(a0, bv.x, acc[m]);
            acc[m] = ffma2(a1, bv.y, acc[m]);
        }
    }

    // BN + lrelu epilogue, write float2 per node
    float2 g2 = *(const float2*)(g + 2 * ft);
    float2 v2 = *(const float2*)(var + 2 * ft);
    float2 m2 = *(const float2*)(mean + 2 * ft);
    float2 bt2 = *(const float2*)(bt + 2 * ft);
    float sc0 = g2.x * rsqrtf(v2.x + BN_EPS);
    float sc1 = g2.y * rsqrtf(v2.y + BN_EPS);
    float sh0 = bt2.x - m2.x * sc0;
    float sh1 = bt2.y - m2.y * sc1;

    #pragma unroll
    for (int m = 0; m < 8; m++) {
        int gn = nodeBase + w * 8 + m;
        if (gn < N_NODES) {
            float2 u = upk(acc[m]);
            float z0 = u.x * sc0 + sh0;
            float z1 = u.y * sc1 + sh1;
            z0 = (z0 >= 0.f) ? z0 : NEG * z0;
            z1 = (z1 >= 0.f) ? z1 : NEG * z1;
            *(float2*)(hout + (size_t)gn * 64 + 2 * ft) = make_float2(z0, z1);
        }
    }
}

// ---------------- pool kernel -------------------------------------------------
__global__ void pool_kernel(const int* __restrict__ batch) {
    int t = blockIdx.x * blockDim.x + threadIdx.x;
    if (t >= N_NODES * 16) return;
    int n = t >> 4, q = t & 15;
    float4 v = *(const float4*)(g_h3 + (size_t)n * 64 + q * 4);
    int gi = __ldg(batch + n);
    red4(g_pool + (size_t)gi * 64 + q * 4, v);
}

// ---------------- final MLP kernel (unchanged: feature-packed f32x2) ----------
#define FINAL_SMEM ((64 * 256 + 64 * 64 * 2) * 4)   // 64KB Ws2 + 32KB vs2 = 96KB

__global__ void __launch_bounds__(512) final_kernel(
    const int* __restrict__ batch,
    const float* __restrict__ bl1,
    const float* __restrict__ Wl2, const float* __restrict__ bl2,
    float* __restrict__ out)
{
    extern __shared__ float smem[];
    float* Ws2 = smem;                // [64 k][256 f]
    float* vs2 = smem + 64 * 256;     // [64 nodes][64 k] duplicated float2

    int tid = threadIdx.x;
    int ft = tid & 31;
    int w = tid >> 5;
    int ng = w & 7;
    int fh = w >> 3;
    int nodeBase = blockIdx.x * 64;

    int fA = fh * 128 + 2 * ft;
    int fB = fA + 64;

    ull biasA = *(const ull*)(bl1 + fA);
    ull biasB = *(const ull*)(bl1 + fB);

    ull acc[2][8];
    #pragma unroll
    for (int m = 0; m < 8; m++) { acc[0][m] = biasA; acc[1][m] = biasB; }

    for (int c = 0; c < 4; c++) {
        __syncthreads();
        #pragma unroll
        for (int it = 0; it < 8; it++) {
            int idx = it * 512 + tid;
            int r = idx >> 6, c4 = idx & 63;
            float4 v = *(const float4*)(g_WT + (size_t)(c * 64 + r) * 256 + c4 * 4);
            *(float4*)(Ws2 + r * 256 + c4 * 4) = v;
        }
        {
            const float* srcArr = (c == 0) ? g_h1 : (c == 1) ? g_h2 : (c == 2) ? g_h3 : g_pool;
            #pragma unroll
            for (int it = 0; it < 8; it++) {
                int idx = it * 512 + tid;
                int n = idx >> 6, k = idx & 63;
                int gn = nodeBase + n;
                float v = 0.f;
                if (gn < N_NODES) {
                    size_t row = (c == 3) ? (size_t)__ldg(batch + gn) * 64 : (size_t)gn * 64;
                    v = srcArr[row + k];
                }
                *(float2*)(vs2 + (n * 64 + k) * 2) = make_float2(v, v);
            }
        }
        __syncthreads();

        #pragma unroll 2
        for (int k = 0; k < 64; k += 2) {
            ull a0k0 = *(const ull*)(Ws2 + k * 256 + fA);
            ull a1k0 = *(const ull*)(Ws2 + k * 256 + fB);
            ull a0k1 = *(const ull*)(Ws2 + (k + 1) * 256 + fA);
            ull a1k1 = *(const ull*)(Ws2 + (k + 1) * 256 + fB);
            const ulonglong2* bvp = (const ulonglong2*)(vs2 + (ng * 8 * 64 + k) * 2);
            #pragma unroll
            for (int m = 0; m < 8; m++) {
                ulonglong2 bv = bvp[m * 32];
                acc[0][m] = ffma2(a0k0, bv.x, acc[0][m]);
                acc[0][m] = ffma2(a0k1, bv.y, acc[0][m]);
                acc[1][m] = ffma2(a1k0, bv.x, acc[1][m]);
                acc[1][m] = ffma2(a1k1, bv.y, acc[1][m]);
            }
        }
    }

    float2 wA = *(const float2*)(Wl2 + fA);
    float2 wB = *(const float2*)(Wl2 + fB);

    float po[8];
    #pragma unroll
    for (int m = 0; m < 8; m++) {
        float2 uA = upk(acc[0][m]);
        float2 uB = upk(acc[1][m]);
        float zA0 = (uA.x >= 0.f) ? uA.x : NEG * uA.x;
        float zA1 = (uA.y >= 0.f) ? uA.y : NEG * uA.y;
        float zB0 = (uB.x >= 0.f) ? uB.x : NEG * uB.x;
        float zB1 = (uB.y >= 0.f) ? uB.y : NEG * uB.y;
        po[m] = zA0 * wA.x + zA1 * wA.y + zB0 * wB.x + zB1 * wB.y;
    }
    #pragma unroll
    for (int m = 0; m < 8; m++) {
        #pragma unroll
        for (int o = 16; o > 0; o >>= 1) po[m] += __shfl_xor_sync(0xffffffffu, po[m], o);
    }

    __shared__ float redsm[2][8][8];
    if (ft < 8) redsm[fh][ng][ft] = po[ft];
    __syncthreads();
    if (fh == 0 && ft < 8) {
        int gn = nodeBase + ng * 8 + ft;
        if (gn < N_NODES) out[gn] = redsm[0][ng][ft] + redsm[1][ng][ft] + bl2[0];
    }
}

// ---------------- launch ------------------------------------------------------
extern "C" void kernel_launch(void* const* d_in, const int* in_sizes, int n_in,
                              void* d_out, int out_size)
{
    const float* x     = (const float*)d_in[0];
    const int*   ei    = (const int*)d_in[1];
    const float* ea    = (const float*)d_in[2];
    const int*   batch = (const int*)d_in[3];

    const float* We[3] = {(const float*)d_in[4],  (const float*)d_in[12], (const float*)d_in[20]};
    const float* be[3] = {(const float*)d_in[5],  (const float*)d_in[13], (const float*)d_in[21]};
    const float* W[3]  = {(const float*)d_in[6],  (const float*)d_in[14], (const float*)d_in[22]};
    const float* b[3]  = {(const float*)d_in[7],  (const float*)d_in[15], (const float*)d_in[23]};
    const float* g[3]  = {(const float*)d_in[8],  (const float*)d_in[16], (const float*)d_in[24]};
    const float* bt[3] = {(const float*)d_in[9],  (const float*)d_in[17], (const float*)d_in[25]};
    const float* mn[3] = {(const float*)d_in[10], (const float*)d_in[18], (const float*)d_in[26]};
    const float* vr[3] = {(const float*)d_in[11], (const float*)d_in[19], (const float*)d_in[27]};
    const float* Wl1 = (const float*)d_in[28];
    const float* bl1 = (const float*)d_in[29];
    const float* Wl2 = (const float*)d_in[30];
    const float* bl2 = (const float*)d_in[31];
    float* out = (float*)d_out;

    const int* src = ei;
    const int* dst = ei + N_EDGES;

    cudaFuncSetAttribute(final_kernel, cudaFuncAttributeMaxDynamicSharedMemorySize, FINAL_SMEM);

    zero_kernel<<<2048, 256>>>();
    transpose_wl1<<<64, 256>>>(Wl1);
    transpose_w64<<<3, 256>>>(W[0], W[1], W[2]);

    for (int l = 0; l < 3; l++) {
        edge_kernel<<<592, 256>>>(l, x, ea, src, dst, We[l], be[l]);
        node_kernel<<<(N_NODES + 63) / 64, 256>>>(l, x, l, b[l], g[l], bt[l], mn[l], vr[l], l + 1);
    }

    pool_kernel<<<(N_NODES * 16 + 255) / 256, 256>>>(batch);

    final_kernel<<<(N_NODES + 63) / 64, 512, FINAL_SMEM>>>(batch, bl1, Wl2, bl2, out);
}